// round 14
// baseline (speedup 1.0000x reference)
#include <cuda_runtime.h>

#define NB   4
#define NH   4
#define NN   2048
#define FIN  128
#define ND   32
#define BHD  (NB*NH)
#define NCH  16      // chunks per (b,h)
#define CHSZ 128     // rows per chunk
#define SEG  512     // sort segment size
#define NSEG (NN/SEG)

// scratch (device globals; no allocation allowed)
__device__ float  g_Wh  [BHD*NN*ND];
__device__ float  g_Wh1 [BHD*NN];
__device__ float  g_Wh2 [BHD*NN];
__device__ unsigned long long g_kv[BHD*NN];   // sorted segments, packed (key|idx)
__device__ int    g_perm[BHD*NN];        // sorted pos -> original row
__device__ float  g_ewn [BHD*NN];        // exp(0.2*w2) in sorted order
__device__ float  g_ewp [BHD*NN];        // exp(w2) in sorted order
__device__ float  g_SnegL[BHD*NN*ND];    // chunk-LOCAL exclusive prefix of exp(.2 w2)*Wh
__device__ float  g_SposL[BHD*NN*ND];    // chunk-LOCAL inclusive suffix of exp(w2)*Wh
__device__ float  g_CnegT[BHD*NCH*ND];   // chunk aggregate vectors
__device__ float  g_CposT[BHD*NCH*ND];
__device__ float  g_OffN [BHD*NCH*ND];   // prefix offsets of chunk aggregates
__device__ float  g_OffP [BHD*NCH*ND];
__device__ float  g_TotN [BHD*ND];       // total neg vector (lo==NN case)
__device__ float  g_pnL[BHD*NN];         // scalar chunk-local prefix/suffix
__device__ float  g_ppL[BHD*NN];
__device__ float  g_pnT[BHD*NCH];        // scalar chunk totals
__device__ float  g_ppT[BHD*NCH];
__device__ float  g_opn[BHD*(NCH+1)];    // scalar chunk-offset prefixes (opn[NCH]=total)
__device__ float  g_opp[BHD*NCH];
__device__ int    g_lo  [BHD*NN];        // per-row threshold position
__device__ float2 g_f12 [BHD*NN];        // (exp(w1), exp(0.2*w1))
__device__ int    g_cnt [BHD];           // k3 completion counters (reset by k2a)

__device__ __forceinline__ float warp_incl_scan(float v, int lane) {
    #pragma unroll
    for (int o = 1; o < 32; o <<= 1) {
        float u = __shfl_up_sync(0xffffffffu, v, o);
        if (lane >= o) v += u;
    }
    return v;
}

__device__ __forceinline__ unsigned long long pack2(float x, float y) {
    unsigned long long r;
    asm("mov.b64 %0, {%1, %2};" : "=l"(r) : "f"(x), "f"(y));
    return r;
}
__device__ __forceinline__ float2 unpack2(unsigned long long v) {
    float2 r;
    asm("mov.b64 {%0, %1}, %2;" : "=f"(r.x), "=f"(r.y) : "l"(v));
    return r;
}
__device__ __forceinline__ void ffma2(unsigned long long& d, unsigned long long a, unsigned long long b) {
    asm("fma.rn.f32x2 %0, %1, %2, %0;" : "+l"(d) : "l"(a), "l"(b));
}

// ---------------- kernel 1: Wh = x @ W[h] (in-block transpose + f32x2 register tile) ----
#define RS 132
#define SM1_X     (FIN*RS*4)
#define SM1_W     (FIN*ND*4)
#define SM1_BYTES (SM1_X + SM1_W + 256)

__global__ void __launch_bounds__(256) k1(const float* __restrict__ x,
                                          const float* __restrict__ W,
                                          const float* __restrict__ a) {
    extern __shared__ char sm1[];
    float* xsT = (float*)sm1;                       // [FIN][RS]
    float* Ws  = (float*)(sm1 + SM1_X);             // [FIN][ND]
    float* a1s = (float*)(sm1 + SM1_X + SM1_W);
    float* a2s = a1s + 32;

    const int h = blockIdx.y, b = blockIdx.z;
    const int n0 = blockIdx.x * 128;
    const int tid = threadIdx.x;

    for (int i = tid; i < FIN*ND; i += 256) Ws[i] = W[h*FIN*ND + i];
    if (tid < 64) {
        float v = a[h*2*ND + tid];
        if (tid < 32) a1s[tid] = v; else a2s[tid-32] = v;
    }
    {
        const int n = tid >> 1, kh = (tid & 1) * 64;
        const float* xr = x + ((size_t)(b*NN + n0 + n))*FIN + kh;
        #pragma unroll
        for (int q = 0; q < 16; q++) {
            float4 v = ((const float4*)xr)[q];
            const int k = kh + 4*q;
            xsT[(k+0)*RS + n] = v.x;
            xsT[(k+1)*RS + n] = v.y;
            xsT[(k+2)*RS + n] = v.z;
            xsT[(k+3)*RS + n] = v.w;
        }
    }
    __syncthreads();

    const int tx = tid & 7, ty = tid >> 3;
    const float* xp = xsT + 4*ty;
    const float* wp = Ws + 4*tx;

    unsigned long long acc[4][2];
    #pragma unroll
    for (int i = 0; i < 4; i++) { acc[i][0] = 0ull; acc[i][1] = 0ull; }

    #pragma unroll 8
    for (int k = 0; k < FIN; k++) {
        float4 xq = *(const float4*)(xp + (size_t)k*RS);
        ulonglong2 wq = *(const ulonglong2*)(wp + k*ND);
        unsigned long long x0 = pack2(xq.x, xq.x);
        unsigned long long x1 = pack2(xq.y, xq.y);
        unsigned long long x2 = pack2(xq.z, xq.z);
        unsigned long long x3 = pack2(xq.w, xq.w);
        ffma2(acc[0][0], x0, wq.x); ffma2(acc[0][1], x0, wq.y);
        ffma2(acc[1][0], x1, wq.x); ffma2(acc[1][1], x1, wq.y);
        ffma2(acc[2][0], x2, wq.x); ffma2(acc[2][1], x2, wq.y);
        ffma2(acc[3][0], x3, wq.x); ffma2(acc[3][1], x3, wq.y);
    }

    const int bh = b*NH + h;
    #pragma unroll
    for (int i = 0; i < 4; i++) {
        float2 p0 = unpack2(acc[i][0]);
        float2 p1 = unpack2(acc[i][1]);
        const int n = n0 + 4*ty + i;
        *(float4*)&g_Wh[((size_t)(bh*NN + n))*ND + 4*tx] = make_float4(p0.x, p0.y, p1.x, p1.y);

        float s1 = p0.x*a1s[4*tx+0] + p0.y*a1s[4*tx+1] + p1.x*a1s[4*tx+2] + p1.y*a1s[4*tx+3];
        float s2 = p0.x*a2s[4*tx+0] + p0.y*a2s[4*tx+1] + p1.x*a2s[4*tx+2] + p1.y*a2s[4*tx+3];
        #pragma unroll
        for (int o2 = 4; o2; o2 >>= 1) {
            s1 += __shfl_xor_sync(0xffffffffu, s1, o2);
            s2 += __shfl_xor_sync(0xffffffffu, s2, o2);
        }
        if (tx == 0) { g_Wh1[bh*NN + n] = s1; g_Wh2[bh*NN + n] = s2; }
    }
}

// ---------------- kernel 2a: sort 512-element segments (4 blocks per bh) ----------------
__global__ void __launch_bounds__(256) k2a() {
    __shared__ unsigned long long kv[SEG];
    const int seg = blockIdx.x, bh = blockIdx.y;
    const int tid = threadIdx.x;
    if (seg == 0 && tid == 0) g_cnt[bh] = 0;   // reset k3 counter for this replay
    const int base = bh*NN + seg*SEG;

    #pragma unroll
    for (int tt = 0; tt < 2; tt++) {
        int e = tid + tt*256;
        unsigned u = __float_as_uint(g_Wh2[base + e]);
        u = (u & 0x80000000u) ? ~u : (u | 0x80000000u);
        kv[e] = ((unsigned long long)u << 32) | (unsigned)(seg*SEG + e);
    }
    __syncthreads();

    for (int k = 2; k <= SEG; k <<= 1) {
        int s = k >> 1;
        for (; s >= 32; s >>= 1) {
            #pragma unroll
            for (int tt = 0; tt < 2; tt++) {
                int t = tid + tt*256;
                int j = t ^ s;
                if (j > t) {
                    unsigned long long va = kv[t], vb = kv[j];
                    bool up = ((t & k) == 0);
                    if ((va > vb) == up) { kv[t] = vb; kv[j] = va; }
                }
            }
            __syncthreads();
        }
        for (; s >= 1; s >>= 1) {
            #pragma unroll
            for (int tt = 0; tt < 2; tt++) {
                int t = tid + tt*256;
                int j = t ^ s;
                if (j > t) {
                    unsigned long long va = kv[t], vb = kv[j];
                    bool up = ((t & k) == 0);
                    if ((va > vb) == up) { kv[t] = vb; kv[j] = va; }
                }
            }
            __syncwarp();
        }
        __syncthreads();
    }

    #pragma unroll
    for (int tt = 0; tt < 2; tt++) {
        int e = tid + tt*256;
        g_kv[base + e] = kv[e];
    }
}

// count elements < T in a sorted 512-segment (10-step gallop, branch-light)
__device__ __forceinline__ int count_less(const unsigned long long* sp, unsigned long long T) {
    int pos = 0;
    #pragma unroll
    for (int st = SEG; st >= 1; st >>= 1) {
        int np = pos + st;
        if (np <= SEG && sp[np-1] < T) pos = np;
    }
    return pos;
}

// ---------------- kernel 2b: rank-merge scatter (incl. exps) + per-row searches ----------------
__global__ void __launch_bounds__(512) k2b() {
    __shared__ unsigned long long skv[NN];
    const int seg = blockIdx.x, bh = blockIdx.y;
    const int tid = threadIdx.x;

    for (int e = tid; e < NN; e += 512) skv[e] = g_kv[bh*NN + e];
    __syncthreads();

    // global rank of own element = local idx + counts in other segments (MLP-3)
    const int e = seg*SEG + tid;
    const unsigned long long v = skv[e];
    int rank = tid;
    #pragma unroll
    for (int s = 0; s < NSEG; s++) {
        if (s == seg) continue;
        rank += count_less(skv + s*SEG, v);
    }
    {
        unsigned u = (unsigned)(v >> 32);
        u = (u & 0x80000000u) ? (u & 0x7fffffffu) : ~u;
        float f = __uint_as_float(u);
        g_ewn [bh*NN + rank] = expf(0.2f * f);
        g_ewp [bh*NN + rank] = expf(f);
        g_perm[bh*NN + rank] = (int)(v & 0xffffffffu);
    }

    // per-row threshold search: lo = #elements with w2 <= -w1 (MLP-4)
    const int i = e;
    const float w1 = g_Wh1[bh*NN + i];
    unsigned ut = __float_as_uint(-w1);
    ut = (ut & 0x80000000u) ? ~ut : (ut | 0x80000000u);
    const unsigned long long T = ((unsigned long long)ut << 32) | 0xffffffffull;
    int lo = 0;
    #pragma unroll
    for (int s = 0; s < NSEG; s++)
        lo += count_less(skv + s*SEG, T);
    g_lo [bh*NN + i] = lo;
    g_f12[bh*NN + i] = make_float2(expf(w1), expf(0.2f * w1));
}

// ---------------- kernel 3: 512-thr, 8 rows/warp, single-wave + last-block offsets ----------
__global__ void __launch_bounds__(512) k3() {
    __shared__ float totn_s[16][35];   // [warp][channel]; col 32 = scalar
    __shared__ float totp_s[16][35];
    __shared__ int isLast;

    const int c = blockIdx.x, bh = blockIdx.y;
    const int tid = threadIdx.x, w = tid >> 5, lane = tid & 31;
    const int hl = lane & 15;
    const int row0 = bh*NN + c*CHSZ + 8*w;   // this warp's 8 rows

    // uniform loads (one request each, broadcast)
    int   p[8];
    float en[8], ep[8];
    #pragma unroll
    for (int r = 0; r < 8; r++) {
        p [r] = g_perm[row0 + r];
        en[r] = g_ewn[row0 + r];
        ep[r] = g_ewp[row0 + r];
    }
    // coalesced gathers (MLP-8): lane = channel
    float wh[8];
    #pragma unroll
    for (int r = 0; r < 8; r++)
        wh[r] = g_Wh[((size_t)(bh*NN + p[r]))*ND + lane];

    float vn[8], vp[8];
    #pragma unroll
    for (int r = 0; r < 8; r++) { vn[r] = en[r]*wh[r]; vp[r] = ep[r]*wh[r]; }
    float sn[8], sp[8];
    sn[0] = 0.f;
    #pragma unroll
    for (int r = 1; r < 8; r++) sn[r] = sn[r-1] + vn[r-1];
    const float totn = sn[7] + vn[7];
    sp[7] = vp[7];
    #pragma unroll
    for (int r = 6; r >= 0; r--) sp[r] = sp[r+1] + vp[r];
    const float totp = sp[0];
    float ssn[8], ssp[8];
    ssn[0] = 0.f;
    #pragma unroll
    for (int r = 1; r < 8; r++) ssn[r] = ssn[r-1] + en[r-1];
    const float stotn = ssn[7] + en[7];
    ssp[7] = ep[7];
    #pragma unroll
    for (int r = 6; r >= 0; r--) ssp[r] = ssp[r+1] + ep[r];
    const float stotp = ssp[0];

    totn_s[w][lane] = totn;
    totp_s[w][lane] = totp;
    if (lane == 0) { totn_s[w][32] = stotn; totp_s[w][32] = stotp; }
    __syncthreads();

    // cross-warp scans: each warp scans channels w (lanes 0-15) and w+16 (lanes 16-31)
    {
        const int ch = (lane < 16) ? w : (w + 16);
        float v1 = totn_s[hl][ch];
        #pragma unroll
        for (int o = 1; o < 16; o <<= 1) {
            float u = __shfl_up_sync(0xffffffffu, v1, o);
            if (hl >= o) v1 += u;
        }
        float e1 = __shfl_up_sync(0xffffffffu, v1, 1); if (hl == 0) e1 = 0.f;
        totn_s[hl][ch] = e1;
        if (hl == 15) g_CnegT[(bh*NCH + c)*ND + ch] = v1;

        float v2 = totp_s[15 - hl][ch];
        #pragma unroll
        for (int o = 1; o < 16; o <<= 1) {
            float u = __shfl_up_sync(0xffffffffu, v2, o);
            if (hl >= o) v2 += u;
        }
        float e2 = __shfl_up_sync(0xffffffffu, v2, 1); if (hl == 0) e2 = 0.f;
        totp_s[15 - hl][ch] = e2;
        if (hl == 15) g_CposT[(bh*NCH + c)*ND + ch] = v2;

        if (w == 0) {   // scalar columns: lanes 0-15 neg, lanes 16-31 pos(reversed)
            float v3 = (lane < 16) ? totn_s[hl][32] : totp_s[15 - hl][32];
            #pragma unroll
            for (int o = 1; o < 16; o <<= 1) {
                float u = __shfl_up_sync(0xffffffffu, v3, o);
                if (hl >= o) v3 += u;
            }
            float e3 = __shfl_up_sync(0xffffffffu, v3, 1); if (hl == 0) e3 = 0.f;
            if (lane < 16) {
                totn_s[hl][32] = e3;
                if (hl == 15) g_pnT[bh*NCH + c] = v3;
            } else {
                totp_s[15 - hl][32] = e3;
                if (hl == 15) g_ppT[bh*NCH + c] = v3;
            }
        }
    }
    __syncthreads();

    const float offn  = totn_s[w][lane];
    const float offp  = totp_s[w][lane];
    const float offsn = totn_s[w][32];
    const float offsp = totp_s[w][32];
    #pragma unroll
    for (int r = 0; r < 8; r++) {
        g_SnegL[((size_t)(row0 + r))*ND + lane] = sn[r] + offn;
        g_SposL[((size_t)(row0 + r))*ND + lane] = sp[r] + offp;
    }
    if (lane == 0) {
        #pragma unroll
        for (int r = 0; r < 8; r++) {
            g_pnL[row0 + r] = ssn[r] + offsn;
            g_ppL[row0 + r] = ssp[r] + offsp;
        }
    }

    // completion counter; last-arriving block of this bh computes chunk offsets (vec + scalar)
    if (tid == 0) {
        __threadfence();
        isLast = (atomicAdd(&g_cnt[bh], 1) == NCH - 1);
    }
    __syncthreads();
    if (isLast) {
        if (w == 0) {
            __threadfence();
            float t[NCH];
            #pragma unroll
            for (int q = 0; q < NCH; q++) t[q] = g_CnegT[(bh*NCH + q)*ND + lane];
            float s = 0.f;
            #pragma unroll
            for (int q = 0; q < NCH; q++) { g_OffN[(bh*NCH + q)*ND + lane] = s; s += t[q]; }
            g_TotN[bh*ND + lane] = s;
        } else if (w == 1) {
            __threadfence();
            float t[NCH];
            #pragma unroll
            for (int q = 0; q < NCH; q++) t[q] = g_CposT[(bh*NCH + q)*ND + lane];
            float s = 0.f;
            #pragma unroll
            for (int q = NCH-1; q >= 0; q--) { g_OffP[(bh*NCH + q)*ND + lane] = s; s += t[q]; }
        } else if (w == 2) {    // scalar neg chunk offsets
            __threadfence();
            float v = (lane < NCH) ? g_pnT[bh*NCH + lane] : 0.f;
            float inc = warp_incl_scan(v, lane);
            float exc = __shfl_up_sync(0xffffffffu, inc, 1); if (lane == 0) exc = 0.f;
            if (lane < NCH) g_opn[bh*(NCH+1) + lane] = exc;
            if (lane == NCH-1) g_opn[bh*(NCH+1) + NCH] = inc;
        } else if (w == 3) {    // scalar pos chunk offsets (suffix)
            __threadfence();
            float v = (lane < NCH) ? g_ppT[bh*NCH + (NCH-1-lane)] : 0.f;
            float inc = warp_incl_scan(v, lane);
            float exc = __shfl_up_sync(0xffffffffu, inc, 1); if (lane == 0) exc = 0.f;
            if (lane < NCH) g_opp[bh*NCH + (NCH-1-lane)] = exc;
        }
    }
}

// ---------------- kernel 5: streaming combine, 8 rows/warp, batched prefetch ----------------
__global__ void __launch_bounds__(256) k5f(float* __restrict__ out) {
    const int bh = blockIdx.y;
    const int b = bh >> 2, h = bh & 3;
    const int tid = threadIdx.x, warp = tid >> 5, lane = tid & 31;
    const int i0 = blockIdx.x*64 + warp*8;

    int lo_l = 0; float f1_l = 0.f, f2_l = 0.f, pn_l = 0.f, pp_l = 0.f;
    if (lane < 8) {
        lo_l = g_lo[bh*NN + i0 + lane];
        float2 f = g_f12[bh*NN + i0 + lane];
        f1_l = f.x; f2_l = f.y;
        if (lo_l < NN) {
            const int c = lo_l >> 7;
            pn_l = g_pnL[bh*NN + lo_l] + g_opn[bh*(NCH+1) + c];
            pp_l = g_ppL[bh*NN + lo_l] + g_opp[bh*NCH + c];
        } else {
            pn_l = g_opn[bh*(NCH+1) + NCH];
            pp_l = 0.f;
        }
    }

    // batched gather phase (MLP up to 16 per lane)
    float sneg[8], spos[8];
    #pragma unroll
    for (int r = 0; r < 8; r++) {
        const int lo = __shfl_sync(0xffffffffu, lo_l, r);
        if (lo < NN) {
            const int c = lo >> 7;
            const size_t ix = ((size_t)(bh*NN) + lo)*ND + lane;
            sneg[r] = g_SnegL[ix] + g_OffN[(bh*NCH + c)*ND + lane];
            spos[r] = g_SposL[ix] + g_OffP[(bh*NCH + c)*ND + lane];
        } else {
            sneg[r] = g_TotN[bh*ND + lane];
            spos[r] = 0.f;
        }
    }

    #pragma unroll
    for (int r = 0; r < 8; r++) {
        const float f1 = __shfl_sync(0xffffffffu, f1_l, r);
        const float f2 = __shfl_sync(0xffffffffu, f2_l, r);
        const float pn = __shfl_sync(0xffffffffu, pn_l, r);
        const float pp = __shfl_sync(0xffffffffu, pp_l, r);
        const int i = i0 + r;
        float num = f2*sneg[r] + f1*spos[r];
        float den = f2*pn + f1*pp;
        float hv = __fdividef(num, den);
        float res = hv > 0.f ? hv : (__expf(hv) - 1.0f);
        out[((size_t)(b*NN + i))*(NH*ND) + h*ND + lane] = res;
    }
}

extern "C" void kernel_launch(void* const* d_in, const int* in_sizes, int n_in,
                              void* d_out, int out_size) {
    (void)in_sizes; (void)n_in; (void)out_size;
    const float* x = (const float*)d_in[0];
    const float* W = (const float*)d_in[1];
    const float* a = (const float*)d_in[2];
    float* out = (float*)d_out;

    static int attr_set = 0;
    if (!attr_set) {
        cudaFuncSetAttribute(k1, cudaFuncAttributeMaxDynamicSharedMemorySize, SM1_BYTES);
        attr_set = 1;
    }

    k1<<<dim3(NN/128, NH, NB), 256, SM1_BYTES>>>(x, W, a);
    k2a<<<dim3(NSEG, BHD), 256>>>();
    k2b<<<dim3(NSEG, BHD), 512>>>();
    k3<<<dim3(NCH, BHD), 512>>>();
    k5f<<<dim3(NN/64, BHD), 256>>>(out);
}

// round 15
// speedup vs baseline: 1.0398x; 1.0398x over previous
#include <cuda_runtime.h>

#define NB   4
#define NH   4
#define NN   2048
#define FIN  128
#define ND   32
#define BHD  (NB*NH)
#define NCH  16      // chunks per (b,h)
#define CHSZ 128     // rows per chunk
#define SEG  512     // sort segment size
#define NSEG (NN/SEG)

// scratch (device globals; no allocation allowed)
__device__ float  g_Wh  [BHD*NN*ND];
__device__ float  g_Wh1 [BHD*NN];
__device__ float  g_Wh2 [BHD*NN];
__device__ unsigned long long g_kv[BHD*NN];   // sorted segments, packed (key|idx)
__device__ int    g_perm[BHD*NN];        // sorted pos -> original row
__device__ float  g_ewn [BHD*NN];        // exp(0.2*w2) in sorted order
__device__ float  g_ewp [BHD*NN];        // exp(w2) in sorted order
__device__ float  g_SnegL[BHD*NN*ND];    // chunk-LOCAL exclusive prefix of exp(.2 w2)*Wh
__device__ float  g_SposL[BHD*NN*ND];    // chunk-LOCAL inclusive suffix of exp(w2)*Wh
__device__ float  g_CnegT[BHD*NCH*ND];   // chunk aggregate vectors
__device__ float  g_CposT[BHD*NCH*ND];
__device__ float  g_OffN [BHD*NCH*ND];   // prefix offsets of chunk aggregates
__device__ float  g_OffP [BHD*NCH*ND];
__device__ float  g_TotN [BHD*ND];       // total neg vector (lo==NN case)
__device__ float  g_pnL[BHD*NN];         // scalar chunk-local prefix/suffix
__device__ float  g_ppL[BHD*NN];
__device__ float  g_pnT[BHD*NCH];        // scalar chunk totals
__device__ float  g_ppT[BHD*NCH];
__device__ float  g_opn[BHD*(NCH+1)];    // scalar chunk-offset prefixes (opn[NCH]=total)
__device__ float  g_opp[BHD*NCH];
__device__ int    g_lo  [BHD*NN];        // per-row threshold position
__device__ float2 g_f12 [BHD*NN];        // (exp(w1), exp(0.2*w1))
__device__ int    g_cnt [BHD];           // k3 completion counters (reset by k2a)

__device__ __forceinline__ void pdl_wait()    { asm volatile("griddepcontrol.wait;" ::: "memory"); }
__device__ __forceinline__ void pdl_trigger() { asm volatile("griddepcontrol.launch_dependents;"); }

__device__ __forceinline__ float warp_incl_scan(float v, int lane) {
    #pragma unroll
    for (int o = 1; o < 32; o <<= 1) {
        float u = __shfl_up_sync(0xffffffffu, v, o);
        if (lane >= o) v += u;
    }
    return v;
}

__device__ __forceinline__ unsigned long long pack2(float x, float y) {
    unsigned long long r;
    asm("mov.b64 %0, {%1, %2};" : "=l"(r) : "f"(x), "f"(y));
    return r;
}
__device__ __forceinline__ float2 unpack2(unsigned long long v) {
    float2 r;
    asm("mov.b64 {%0, %1}, %2;" : "=f"(r.x), "=f"(r.y) : "l"(v));
    return r;
}
__device__ __forceinline__ void ffma2(unsigned long long& d, unsigned long long a, unsigned long long b) {
    asm("fma.rn.f32x2 %0, %1, %2, %0;" : "+l"(d) : "l"(a), "l"(b));
}

// ---------------- kernel 1: Wh = x @ W[h] (in-block transpose + f32x2 register tile) ----
#define RS 132
#define SM1_X     (FIN*RS*4)
#define SM1_W     (FIN*ND*4)
#define SM1_BYTES (SM1_X + SM1_W + 256)

__global__ void __launch_bounds__(256) k1(const float* __restrict__ x,
                                          const float* __restrict__ W,
                                          const float* __restrict__ a) {
    extern __shared__ char sm1[];
    float* xsT = (float*)sm1;                       // [FIN][RS]
    float* Ws  = (float*)(sm1 + SM1_X);             // [FIN][ND]
    float* a1s = (float*)(sm1 + SM1_X + SM1_W);
    float* a2s = a1s + 32;

    pdl_trigger();   // no predecessor; let k2a prologue overlap

    const int h = blockIdx.y, b = blockIdx.z;
    const int n0 = blockIdx.x * 128;
    const int tid = threadIdx.x;

    for (int i = tid; i < FIN*ND; i += 256) Ws[i] = W[h*FIN*ND + i];
    if (tid < 64) {
        float v = a[h*2*ND + tid];
        if (tid < 32) a1s[tid] = v; else a2s[tid-32] = v;
    }
    {
        const int n = tid >> 1, kh = (tid & 1) * 64;
        const float* xr = x + ((size_t)(b*NN + n0 + n))*FIN + kh;
        #pragma unroll
        for (int q = 0; q < 16; q++) {
            float4 v = ((const float4*)xr)[q];
            const int k = kh + 4*q;
            xsT[(k+0)*RS + n] = v.x;
            xsT[(k+1)*RS + n] = v.y;
            xsT[(k+2)*RS + n] = v.z;
            xsT[(k+3)*RS + n] = v.w;
        }
    }
    __syncthreads();

    const int tx = tid & 7, ty = tid >> 3;
    const float* xp = xsT + 4*ty;
    const float* wp = Ws + 4*tx;

    unsigned long long acc[4][2];
    #pragma unroll
    for (int i = 0; i < 4; i++) { acc[i][0] = 0ull; acc[i][1] = 0ull; }

    #pragma unroll 8
    for (int k = 0; k < FIN; k++) {
        float4 xq = *(const float4*)(xp + (size_t)k*RS);
        ulonglong2 wq = *(const ulonglong2*)(wp + k*ND);
        unsigned long long x0 = pack2(xq.x, xq.x);
        unsigned long long x1 = pack2(xq.y, xq.y);
        unsigned long long x2 = pack2(xq.z, xq.z);
        unsigned long long x3 = pack2(xq.w, xq.w);
        ffma2(acc[0][0], x0, wq.x); ffma2(acc[0][1], x0, wq.y);
        ffma2(acc[1][0], x1, wq.x); ffma2(acc[1][1], x1, wq.y);
        ffma2(acc[2][0], x2, wq.x); ffma2(acc[2][1], x2, wq.y);
        ffma2(acc[3][0], x3, wq.x); ffma2(acc[3][1], x3, wq.y);
    }

    const int bh = b*NH + h;
    #pragma unroll
    for (int i = 0; i < 4; i++) {
        float2 p0 = unpack2(acc[i][0]);
        float2 p1 = unpack2(acc[i][1]);
        const int n = n0 + 4*ty + i;
        *(float4*)&g_Wh[((size_t)(bh*NN + n))*ND + 4*tx] = make_float4(p0.x, p0.y, p1.x, p1.y);

        float s1 = p0.x*a1s[4*tx+0] + p0.y*a1s[4*tx+1] + p1.x*a1s[4*tx+2] + p1.y*a1s[4*tx+3];
        float s2 = p0.x*a2s[4*tx+0] + p0.y*a2s[4*tx+1] + p1.x*a2s[4*tx+2] + p1.y*a2s[4*tx+3];
        #pragma unroll
        for (int o2 = 4; o2; o2 >>= 1) {
            s1 += __shfl_xor_sync(0xffffffffu, s1, o2);
            s2 += __shfl_xor_sync(0xffffffffu, s2, o2);
        }
        if (tx == 0) { g_Wh1[bh*NN + n] = s1; g_Wh2[bh*NN + n] = s2; }
    }
}

// ---------------- kernel 2a: sort 512-element segments (4 blocks per bh) ----------------
__global__ void __launch_bounds__(256) k2a() {
    __shared__ unsigned long long kv[SEG];
    const int seg = blockIdx.x, bh = blockIdx.y;
    const int tid = threadIdx.x;
    if (seg == 0 && tid == 0) g_cnt[bh] = 0;   // pre-wait: k1 doesn't touch g_cnt
    const int base = bh*NN + seg*SEG;

    pdl_wait();      // k1 complete
    pdl_trigger();   // k2b may launch; its pre-wait reads k1 outputs (now complete)

    #pragma unroll
    for (int tt = 0; tt < 2; tt++) {
        int e = tid + tt*256;
        unsigned u = __float_as_uint(g_Wh2[base + e]);
        u = (u & 0x80000000u) ? ~u : (u | 0x80000000u);
        kv[e] = ((unsigned long long)u << 32) | (unsigned)(seg*SEG + e);
    }
    __syncthreads();

    for (int k = 2; k <= SEG; k <<= 1) {
        int s = k >> 1;
        for (; s >= 32; s >>= 1) {
            #pragma unroll
            for (int tt = 0; tt < 2; tt++) {
                int t = tid + tt*256;
                int j = t ^ s;
                if (j > t) {
                    unsigned long long va = kv[t], vb = kv[j];
                    bool up = ((t & k) == 0);
                    if ((va > vb) == up) { kv[t] = vb; kv[j] = va; }
                }
            }
            __syncthreads();
        }
        for (; s >= 1; s >>= 1) {
            #pragma unroll
            for (int tt = 0; tt < 2; tt++) {
                int t = tid + tt*256;
                int j = t ^ s;
                if (j > t) {
                    unsigned long long va = kv[t], vb = kv[j];
                    bool up = ((t & k) == 0);
                    if ((va > vb) == up) { kv[t] = vb; kv[j] = va; }
                }
            }
            __syncwarp();
        }
        __syncthreads();
    }

    #pragma unroll
    for (int tt = 0; tt < 2; tt++) {
        int e = tid + tt*256;
        g_kv[base + e] = kv[e];
    }
}

// count elements < T in a sorted 512-segment (10-step gallop, branch-light)
__device__ __forceinline__ int count_less(const unsigned long long* sp, unsigned long long T) {
    int pos = 0;
    #pragma unroll
    for (int st = SEG; st >= 1; st >>= 1) {
        int np = pos + st;
        if (np <= SEG && sp[np-1] < T) pos = np;
    }
    return pos;
}

// ---------------- kernel 2b: rank-merge scatter (incl. exps) + per-row searches ----------------
__global__ void __launch_bounds__(512) k2b() {
    __shared__ unsigned long long skv[NN];
    const int seg = blockIdx.x, bh = blockIdx.y;
    const int tid = threadIdx.x;
    const int e = seg*SEG + tid;

    // pre-wait: k1 outputs are complete (guaranteed via k2a's wait->trigger order).
    // Overlaps k2a's sort.
    const float w1 = g_Wh1[bh*NN + e];
    g_f12[bh*NN + e] = make_float2(expf(w1), expf(0.2f * w1));
    unsigned ut = __float_as_uint(-w1);
    ut = (ut & 0x80000000u) ? ~ut : (ut | 0x80000000u);
    const unsigned long long T = ((unsigned long long)ut << 32) | 0xffffffffull;

    pdl_wait();      // k2a complete
    pdl_trigger();

    for (int q = tid; q < NN; q += 512) skv[q] = g_kv[bh*NN + q];
    __syncthreads();

    // global rank of own element = local idx + counts in other segments (MLP-3)
    const unsigned long long v = skv[e];
    int rank = tid;
    #pragma unroll
    for (int s = 0; s < NSEG; s++) {
        if (s == seg) continue;
        rank += count_less(skv + s*SEG, v);
    }
    {
        unsigned u = (unsigned)(v >> 32);
        u = (u & 0x80000000u) ? (u & 0x7fffffffu) : ~u;
        float f = __uint_as_float(u);
        g_ewn [bh*NN + rank] = expf(0.2f * f);
        g_ewp [bh*NN + rank] = expf(f);
        g_perm[bh*NN + rank] = (int)(v & 0xffffffffu);
    }

    // per-row threshold search: lo = #elements with w2 <= -w1 (MLP-4)
    int lo = 0;
    #pragma unroll
    for (int s = 0; s < NSEG; s++)
        lo += count_less(skv + s*SEG, T);
    g_lo[bh*NN + e] = lo;
}

// ---------------- kernel 3: warp-per-rowgroup 2-level scan + last-block offsets ----------------
__global__ void __launch_bounds__(1024) k3() {
    __shared__ float totn_s[32][35];   // [warp][channel] totals; col 32 = scalar
    __shared__ float totp_s[32][35];
    __shared__ int isLast;

    pdl_wait();      // k2b complete
    pdl_trigger();   // k5f may launch; its pre-wait reads k2b outputs (complete)

    const int c = blockIdx.x, bh = blockIdx.y;
    const int tid = threadIdx.x, w = tid >> 5, lane = tid & 31;
    const int row0 = bh*NN + c*CHSZ + 4*w;   // this warp's 4 rows (global index)

    // lane0 wide loads, broadcast to warp
    int   p[4];
    float en[4], ep[4];
    if (lane == 0) {
        int4   p4 = *(const int4*)  &g_perm[row0];
        float4 e1 = *(const float4*)&g_ewn[row0];
        float4 e2 = *(const float4*)&g_ewp[row0];
        p[0]=p4.x; p[1]=p4.y; p[2]=p4.z; p[3]=p4.w;
        en[0]=e1.x; en[1]=e1.y; en[2]=e1.z; en[3]=e1.w;
        ep[0]=e2.x; ep[1]=e2.y; ep[2]=e2.z; ep[3]=e2.w;
    }
    #pragma unroll
    for (int r = 0; r < 4; r++) {
        p [r] = __shfl_sync(0xffffffffu, p [r], 0);
        en[r] = __shfl_sync(0xffffffffu, en[r], 0);
        ep[r] = __shfl_sync(0xffffffffu, ep[r], 0);
    }

    // coalesced gathers: lane = channel
    float wh[4];
    #pragma unroll
    for (int r = 0; r < 4; r++)
        wh[r] = g_Wh[((size_t)(bh*NN + p[r]))*ND + lane];

    // register-serial prefix (neg, exclusive) and suffix (pos, inclusive) over 4 rows
    float vn[4], vp[4];
    #pragma unroll
    for (int r = 0; r < 4; r++) { vn[r] = en[r]*wh[r]; vp[r] = ep[r]*wh[r]; }
    float sn[4], sp[4];
    sn[0] = 0.f;   sn[1] = vn[0]; sn[2] = sn[1]+vn[1]; sn[3] = sn[2]+vn[2];
    const float totn = sn[3] + vn[3];
    sp[3] = vp[3]; sp[2] = sp[3]+vp[2]; sp[1] = sp[2]+vp[1]; sp[0] = sp[1]+vp[0];
    const float totp = sp[0];
    // scalar analogues
    float ssn[4], ssp[4];
    ssn[0] = 0.f;   ssn[1] = en[0]; ssn[2] = ssn[1]+en[1]; ssn[3] = ssn[2]+en[2];
    const float stotn = ssn[3] + en[3];
    ssp[3] = ep[3]; ssp[2] = ssp[3]+ep[2]; ssp[1] = ssp[2]+ep[1]; ssp[0] = ssp[1]+ep[0];
    const float stotp = ssp[0];

    totn_s[w][lane] = totn;
    totp_s[w][lane] = totp;
    if (lane == 0) { totn_s[w][32] = stotn; totp_s[w][32] = stotp; }
    __syncthreads();

    // cross-warp scans: warp w scans channel w (stride-35 = conflict-free)
    {
        float v1 = totn_s[lane][w];
        float i1 = warp_incl_scan(v1, lane);
        float e1 = __shfl_up_sync(0xffffffffu, i1, 1); if (lane == 0) e1 = 0.f;
        totn_s[lane][w] = e1;
        if (lane == 31) g_CnegT[(bh*NCH + c)*ND + w] = i1;

        float v2 = totp_s[31 - lane][w];
        float i2 = warp_incl_scan(v2, lane);
        float e2 = __shfl_up_sync(0xffffffffu, i2, 1); if (lane == 0) e2 = 0.f;
        totp_s[31 - lane][w] = e2;
        if (lane == 31) g_CposT[(bh*NCH + c)*ND + w] = i2;

        if (w == 0) {           // scalar neg column
            float v3 = totn_s[lane][32];
            float i3 = warp_incl_scan(v3, lane);
            float e3 = __shfl_up_sync(0xffffffffu, i3, 1); if (lane == 0) e3 = 0.f;
            totn_s[lane][32] = e3;
            if (lane == 31) g_pnT[bh*NCH + c] = i3;
        } else if (w == 1) {    // scalar pos column (suffix)
            float v3 = totp_s[31 - lane][32];
            float i3 = warp_incl_scan(v3, lane);
            float e3 = __shfl_up_sync(0xffffffffu, i3, 1); if (lane == 0) e3 = 0.f;
            totp_s[31 - lane][32] = e3;
            if (lane == 31) g_ppT[bh*NCH + c] = i3;
        }
    }
    __syncthreads();

    const float offn  = totn_s[w][lane];
    const float offp  = totp_s[w][lane];
    const float offsn = totn_s[w][32];
    const float offsp = totp_s[w][32];
    #pragma unroll
    for (int r = 0; r < 4; r++) {
        g_SnegL[((size_t)(row0 + r))*ND + lane] = sn[r] + offn;
        g_SposL[((size_t)(row0 + r))*ND + lane] = sp[r] + offp;
    }
    if (lane == 0) {
        #pragma unroll
        for (int r = 0; r < 4; r++) {
            g_pnL[row0 + r] = ssn[r] + offsn;
            g_ppL[row0 + r] = ssp[r] + offsp;
        }
    }

    // completion counter; last-arriving block of this bh computes chunk offsets (vec + scalar)
    if (tid == 0) {
        __threadfence();
        isLast = (atomicAdd(&g_cnt[bh], 1) == NCH - 1);
    }
    __syncthreads();
    if (isLast) {
        if (w == 0) {
            __threadfence();
            float t[NCH];
            #pragma unroll
            for (int q = 0; q < NCH; q++) t[q] = g_CnegT[(bh*NCH + q)*ND + lane];
            float s = 0.f;
            #pragma unroll
            for (int q = 0; q < NCH; q++) { g_OffN[(bh*NCH + q)*ND + lane] = s; s += t[q]; }
            g_TotN[bh*ND + lane] = s;
        } else if (w == 1) {
            __threadfence();
            float t[NCH];
            #pragma unroll
            for (int q = 0; q < NCH; q++) t[q] = g_CposT[(bh*NCH + q)*ND + lane];
            float s = 0.f;
            #pragma unroll
            for (int q = NCH-1; q >= 0; q--) { g_OffP[(bh*NCH + q)*ND + lane] = s; s += t[q]; }
        } else if (w == 2) {    // scalar neg chunk offsets
            __threadfence();
            float v = (lane < NCH) ? g_pnT[bh*NCH + lane] : 0.f;
            float inc = warp_incl_scan(v, lane);
            float exc = __shfl_up_sync(0xffffffffu, inc, 1); if (lane == 0) exc = 0.f;
            if (lane < NCH) g_opn[bh*(NCH+1) + lane] = exc;
            if (lane == NCH-1) g_opn[bh*(NCH+1) + NCH] = inc;
        } else if (w == 3) {    // scalar pos chunk offsets (suffix)
            __threadfence();
            float v = (lane < NCH) ? g_ppT[bh*NCH + (NCH-1-lane)] : 0.f;
            float inc = warp_incl_scan(v, lane);
            float exc = __shfl_up_sync(0xffffffffu, inc, 1); if (lane == 0) exc = 0.f;
            if (lane < NCH) g_opp[bh*NCH + (NCH-1-lane)] = exc;
        }
    }
}

// ---------------- kernel 5: pure streaming combine (PDL pre-wait prefetch) ----------------
__global__ void __launch_bounds__(256) k5f(float* __restrict__ out) {
    const int bh = blockIdx.y;
    const int b = bh >> 2, h = bh & 3;
    const int tid = threadIdx.x, warp = tid >> 5, lane = tid & 31;
    const int i0 = blockIdx.x*32 + warp*4;

    // pre-wait: g_lo/g_f12 are k2b outputs, complete by transitivity (k3 waited).
    // These loads overlap k3's execution.
    int lo_l = 0; float f1_l = 0.f, f2_l = 0.f;
    if (lane < 4) {
        lo_l = g_lo[bh*NN + i0 + lane];
        float2 f = g_f12[bh*NN + i0 + lane];
        f1_l = f.x; f2_l = f.y;
    }

    pdl_wait();      // k3 complete

    float pn_l = 0.f, pp_l = 0.f;
    if (lane < 4) {
        if (lo_l < NN) {
            const int c = lo_l >> 7;
            pn_l = g_pnL[bh*NN + lo_l] + g_opn[bh*(NCH+1) + c];
            pp_l = g_ppL[bh*NN + lo_l] + g_opp[bh*NCH + c];
        } else {
            pn_l = g_opn[bh*(NCH+1) + NCH];
            pp_l = 0.f;
        }
    }

    #pragma unroll
    for (int r = 0; r < 4; r++) {
        const int lo = __shfl_sync(0xffffffffu, lo_l, r);
        const float f1 = __shfl_sync(0xffffffffu, f1_l, r);
        const float f2 = __shfl_sync(0xffffffffu, f2_l, r);
        const float pn = __shfl_sync(0xffffffffu, pn_l, r);
        const float pp = __shfl_sync(0xffffffffu, pp_l, r);
        const int i = i0 + r;
        float sneg, spos;
        if (lo < NN) {
            const int c = lo >> 7;
            const size_t ix = ((size_t)(bh*NN) + lo)*ND + lane;
            sneg = g_SnegL[ix] + g_OffN[(bh*NCH + c)*ND + lane];
            spos = g_SposL[ix] + g_OffP[(bh*NCH + c)*ND + lane];
        } else {
            sneg = g_TotN[bh*ND + lane];
            spos = 0.f;
        }
        float num = f2*sneg + f1*spos;
        float den = f2*pn + f1*pp;
        float hv = __fdividef(num, den);
        float res = hv > 0.f ? hv : (__expf(hv) - 1.0f);
        out[((size_t)(b*NN + i))*(NH*ND) + h*ND + lane] = res;
    }
}

// ---------------- host ----------------
template <typename... Args, typename F>
static inline void launch_pdl(F func, dim3 grid, dim3 block, Args... args) {
    cudaLaunchConfig_t cfg = {};
    cfg.gridDim = grid;
    cfg.blockDim = block;
    cfg.dynamicSmemBytes = 0;
    cfg.stream = 0;
    cudaLaunchAttribute attr[1];
    attr[0].id = cudaLaunchAttributeProgrammaticStreamSerialization;
    attr[0].val.programmaticStreamSerializationAllowed = 1;
    cfg.attrs = attr;
    cfg.numAttrs = 1;
    cudaLaunchKernelEx(&cfg, func, args...);
}

extern "C" void kernel_launch(void* const* d_in, const int* in_sizes, int n_in,
                              void* d_out, int out_size) {
    (void)in_sizes; (void)n_in; (void)out_size;
    const float* x = (const float*)d_in[0];
    const float* W = (const float*)d_in[1];
    const float* a = (const float*)d_in[2];
    float* out = (float*)d_out;

    static int attr_set = 0;
    if (!attr_set) {
        cudaFuncSetAttribute(k1, cudaFuncAttributeMaxDynamicSharedMemorySize, SM1_BYTES);
        attr_set = 1;
    }

    k1<<<dim3(NN/128, NH, NB), 256, SM1_BYTES>>>(x, W, a);
    launch_pdl(k2a, dim3(NSEG, BHD), dim3(256));
    launch_pdl(k2b, dim3(NSEG, BHD), dim3(512));
    launch_pdl(k3,  dim3(NCH, BHD),  dim3(1024));
    launch_pdl(k5f, dim3(NN/32, BHD), dim3(256), out);
}

// round 16
// speedup vs baseline: 1.0576x; 1.0171x over previous
#include <cuda_runtime.h>

#define NB   4
#define NH   4
#define NN   2048
#define FIN  128
#define ND   32
#define BHD  (NB*NH)
#define NCH  16      // chunks per (b,h)
#define CHSZ 128     // rows per chunk
#define SEG  512     // sort segment size
#define NSEG (NN/SEG)

// scratch (device globals; no allocation allowed)
__device__ float  g_Wh  [BHD*NN*ND];
__device__ float  g_Wh1 [BHD*NN];
__device__ float  g_Wh2 [BHD*NN];
__device__ unsigned long long g_kv[BHD*NN];   // sorted segments, packed (key|idx)
__device__ int    g_perm[BHD*NN];        // sorted pos -> original row
__device__ float2 g_ew  [BHD*NN];        // (exp(0.2*w2), exp(w2)) in sorted order
__device__ float2 g_S   [BHD*NN*ND];     // (chunk-local Sneg prefix, Spos suffix)
__device__ float  g_CnegT[BHD*NCH*ND];   // chunk aggregate vectors
__device__ float  g_CposT[BHD*NCH*ND];
__device__ float2 g_Off [BHD*NCH*ND];    // (OffN, OffP) chunk offset vectors
__device__ float2 g_Tot2[BHD*ND];        // (TotN, 0) for lo==NN case
__device__ float2 g_pL  [BHD*NN];        // scalar chunk-local (pn, pp)
__device__ float  g_pnT[BHD*NCH];        // scalar chunk totals
__device__ float  g_ppT[BHD*NCH];
__device__ float  g_opn[BHD*(NCH+1)];    // scalar chunk-offset prefixes (opn[NCH]=total)
__device__ float  g_opp[BHD*NCH];
__device__ int    g_lo  [BHD*NN];        // per-row threshold position
__device__ float2 g_f12 [BHD*NN];        // (exp(w1), exp(0.2*w1))
__device__ int    g_cnt [BHD];           // k3 completion counters (reset by k2a)

__device__ __forceinline__ void pdl_wait()    { asm volatile("griddepcontrol.wait;" ::: "memory"); }
__device__ __forceinline__ void pdl_trigger() { asm volatile("griddepcontrol.launch_dependents;"); }

__device__ __forceinline__ float warp_incl_scan(float v, int lane) {
    #pragma unroll
    for (int o = 1; o < 32; o <<= 1) {
        float u = __shfl_up_sync(0xffffffffu, v, o);
        if (lane >= o) v += u;
    }
    return v;
}

__device__ __forceinline__ unsigned long long pack2(float x, float y) {
    unsigned long long r;
    asm("mov.b64 %0, {%1, %2};" : "=l"(r) : "f"(x), "f"(y));
    return r;
}
__device__ __forceinline__ float2 unpack2(unsigned long long v) {
    float2 r;
    asm("mov.b64 {%0, %1}, %2;" : "=f"(r.x), "=f"(r.y) : "l"(v));
    return r;
}
__device__ __forceinline__ void ffma2(unsigned long long& d, unsigned long long a, unsigned long long b) {
    asm("fma.rn.f32x2 %0, %1, %2, %0;" : "+l"(d) : "l"(a), "l"(b));
}

// ---------------- kernel 1: Wh = x @ W[h] (in-block transpose + f32x2 register tile) ----
#define RS 132
#define SM1_X     (FIN*RS*4)
#define SM1_W     (FIN*ND*4)
#define SM1_BYTES (SM1_X + SM1_W + 256)

__global__ void __launch_bounds__(256) k1(const float* __restrict__ x,
                                          const float* __restrict__ W,
                                          const float* __restrict__ a) {
    extern __shared__ char sm1[];
    float* xsT = (float*)sm1;                       // [FIN][RS]
    float* Ws  = (float*)(sm1 + SM1_X);             // [FIN][ND]
    float* a1s = (float*)(sm1 + SM1_X + SM1_W);
    float* a2s = a1s + 32;

    pdl_trigger();   // no predecessor; let k2a prologue overlap

    const int h = blockIdx.y, b = blockIdx.z;
    const int n0 = blockIdx.x * 128;
    const int tid = threadIdx.x;

    for (int i = tid; i < FIN*ND; i += 256) Ws[i] = W[h*FIN*ND + i];
    if (tid < 64) {
        float v = a[h*2*ND + tid];
        if (tid < 32) a1s[tid] = v; else a2s[tid-32] = v;
    }
    {
        const int n = tid >> 1, kh = (tid & 1) * 64;
        const float* xr = x + ((size_t)(b*NN + n0 + n))*FIN + kh;
        #pragma unroll
        for (int q = 0; q < 16; q++) {
            float4 v = ((const float4*)xr)[q];
            const int k = kh + 4*q;
            xsT[(k+0)*RS + n] = v.x;
            xsT[(k+1)*RS + n] = v.y;
            xsT[(k+2)*RS + n] = v.z;
            xsT[(k+3)*RS + n] = v.w;
        }
    }
    __syncthreads();

    const int tx = tid & 7, ty = tid >> 3;
    const float* xp = xsT + 4*ty;
    const float* wp = Ws + 4*tx;

    unsigned long long acc[4][2];
    #pragma unroll
    for (int i = 0; i < 4; i++) { acc[i][0] = 0ull; acc[i][1] = 0ull; }

    #pragma unroll 8
    for (int k = 0; k < FIN; k++) {
        float4 xq = *(const float4*)(xp + (size_t)k*RS);
        ulonglong2 wq = *(const ulonglong2*)(wp + k*ND);
        unsigned long long x0 = pack2(xq.x, xq.x);
        unsigned long long x1 = pack2(xq.y, xq.y);
        unsigned long long x2 = pack2(xq.z, xq.z);
        unsigned long long x3 = pack2(xq.w, xq.w);
        ffma2(acc[0][0], x0, wq.x); ffma2(acc[0][1], x0, wq.y);
        ffma2(acc[1][0], x1, wq.x); ffma2(acc[1][1], x1, wq.y);
        ffma2(acc[2][0], x2, wq.x); ffma2(acc[2][1], x2, wq.y);
        ffma2(acc[3][0], x3, wq.x); ffma2(acc[3][1], x3, wq.y);
    }

    const int bh = b*NH + h;
    #pragma unroll
    for (int i = 0; i < 4; i++) {
        float2 p0 = unpack2(acc[i][0]);
        float2 p1 = unpack2(acc[i][1]);
        const int n = n0 + 4*ty + i;
        *(float4*)&g_Wh[((size_t)(bh*NN + n))*ND + 4*tx] = make_float4(p0.x, p0.y, p1.x, p1.y);

        float s1 = p0.x*a1s[4*tx+0] + p0.y*a1s[4*tx+1] + p1.x*a1s[4*tx+2] + p1.y*a1s[4*tx+3];
        float s2 = p0.x*a2s[4*tx+0] + p0.y*a2s[4*tx+1] + p1.x*a2s[4*tx+2] + p1.y*a2s[4*tx+3];
        #pragma unroll
        for (int o2 = 4; o2; o2 >>= 1) {
            s1 += __shfl_xor_sync(0xffffffffu, s1, o2);
            s2 += __shfl_xor_sync(0xffffffffu, s2, o2);
        }
        if (tx == 0) { g_Wh1[bh*NN + n] = s1; g_Wh2[bh*NN + n] = s2; }
    }
}

// ---------------- kernel 2a: sort 512-element segments (4 blocks per bh) ----------------
__global__ void __launch_bounds__(256) k2a() {
    __shared__ unsigned long long kv[SEG];
    const int seg = blockIdx.x, bh = blockIdx.y;
    const int tid = threadIdx.x;
    if (seg == 0 && tid == 0) g_cnt[bh] = 0;   // pre-wait: k1 doesn't touch g_cnt
    const int base = bh*NN + seg*SEG;

    pdl_wait();      // k1 complete
    pdl_trigger();   // k2b may launch; its pre-wait reads k1 outputs (now complete)

    #pragma unroll
    for (int tt = 0; tt < 2; tt++) {
        int e = tid + tt*256;
        unsigned u = __float_as_uint(g_Wh2[base + e]);
        u = (u & 0x80000000u) ? ~u : (u | 0x80000000u);
        kv[e] = ((unsigned long long)u << 32) | (unsigned)(seg*SEG + e);
    }
    __syncthreads();

    for (int k = 2; k <= SEG; k <<= 1) {
        int s = k >> 1;
        for (; s >= 32; s >>= 1) {
            #pragma unroll
            for (int tt = 0; tt < 2; tt++) {
                int t = tid + tt*256;
                int j = t ^ s;
                if (j > t) {
                    unsigned long long va = kv[t], vb = kv[j];
                    bool up = ((t & k) == 0);
                    if ((va > vb) == up) { kv[t] = vb; kv[j] = va; }
                }
            }
            __syncthreads();
        }
        for (; s >= 1; s >>= 1) {
            #pragma unroll
            for (int tt = 0; tt < 2; tt++) {
                int t = tid + tt*256;
                int j = t ^ s;
                if (j > t) {
                    unsigned long long va = kv[t], vb = kv[j];
                    bool up = ((t & k) == 0);
                    if ((va > vb) == up) { kv[t] = vb; kv[j] = va; }
                }
            }
            __syncwarp();
        }
        __syncthreads();
    }

    #pragma unroll
    for (int tt = 0; tt < 2; tt++) {
        int e = tid + tt*256;
        g_kv[base + e] = kv[e];
    }
}

// count elements < T in a sorted 512-segment (10-step gallop, branch-light)
__device__ __forceinline__ int count_less(const unsigned long long* sp, unsigned long long T) {
    int pos = 0;
    #pragma unroll
    for (int st = SEG; st >= 1; st >>= 1) {
        int np = pos + st;
        if (np <= SEG && sp[np-1] < T) pos = np;
    }
    return pos;
}

// ---------------- kernel 2b: rank-merge scatter (incl. exps) + per-row searches ----------------
__global__ void __launch_bounds__(512) k2b() {
    __shared__ unsigned long long skv[NN];
    const int seg = blockIdx.x, bh = blockIdx.y;
    const int tid = threadIdx.x;
    const int e = seg*SEG + tid;

    // pre-wait: k1 outputs are complete (guaranteed via k2a's wait->trigger order).
    // Overlaps k2a's sort.
    const float w1 = g_Wh1[bh*NN + e];
    g_f12[bh*NN + e] = make_float2(expf(w1), expf(0.2f * w1));
    unsigned ut = __float_as_uint(-w1);
    ut = (ut & 0x80000000u) ? ~ut : (ut | 0x80000000u);
    const unsigned long long T = ((unsigned long long)ut << 32) | 0xffffffffull;

    pdl_wait();      // k2a complete
    pdl_trigger();

    for (int q = tid; q < NN; q += 512) skv[q] = g_kv[bh*NN + q];
    __syncthreads();

    // global rank of own element = local idx + counts in other segments (MLP-3)
    const unsigned long long v = skv[e];
    int rank = tid;
    #pragma unroll
    for (int s = 0; s < NSEG; s++) {
        if (s == seg) continue;
        rank += count_less(skv + s*SEG, v);
    }
    {
        unsigned u = (unsigned)(v >> 32);
        u = (u & 0x80000000u) ? (u & 0x7fffffffu) : ~u;
        float f = __uint_as_float(u);
        g_ew  [bh*NN + rank] = make_float2(expf(0.2f * f), expf(f));
        g_perm[bh*NN + rank] = (int)(v & 0xffffffffu);
    }

    // per-row threshold search: lo = #elements with w2 <= -w1 (MLP-4)
    int lo = 0;
    #pragma unroll
    for (int s = 0; s < NSEG; s++)
        lo += count_less(skv + s*SEG, T);
    g_lo[bh*NN + e] = lo;
}

// ---------------- kernel 3: warp-per-rowgroup 2-level scan + last-block offsets ----------------
__global__ void __launch_bounds__(1024) k3() {
    __shared__ float totn_s[32][35];   // [warp][channel] totals; col 32 = scalar
    __shared__ float totp_s[32][35];
    __shared__ int isLast;

    pdl_wait();      // k2b complete
    pdl_trigger();   // k5f may launch; its pre-wait reads k2b outputs (complete)

    const int c = blockIdx.x, bh = blockIdx.y;
    const int tid = threadIdx.x, w = tid >> 5, lane = tid & 31;
    const int row0 = bh*NN + c*CHSZ + 4*w;   // this warp's 4 rows (global index)

    // lane0 wide loads, broadcast to warp
    int   p[4];
    float en[4], ep[4];
    if (lane == 0) {
        int4   p4 = *(const int4*)  &g_perm[row0];
        float4 ea = *(const float4*)&g_ew[row0];       // rows 0,1: (en0,ep0,en1,ep1)
        float4 eb = *(const float4*)&g_ew[row0 + 2];   // rows 2,3
        p[0]=p4.x; p[1]=p4.y; p[2]=p4.z; p[3]=p4.w;
        en[0]=ea.x; ep[0]=ea.y; en[1]=ea.z; ep[1]=ea.w;
        en[2]=eb.x; ep[2]=eb.y; en[3]=eb.z; ep[3]=eb.w;
    }
    #pragma unroll
    for (int r = 0; r < 4; r++) {
        p [r] = __shfl_sync(0xffffffffu, p [r], 0);
        en[r] = __shfl_sync(0xffffffffu, en[r], 0);
        ep[r] = __shfl_sync(0xffffffffu, ep[r], 0);
    }

    // coalesced gathers: lane = channel
    float wh[4];
    #pragma unroll
    for (int r = 0; r < 4; r++)
        wh[r] = g_Wh[((size_t)(bh*NN + p[r]))*ND + lane];

    // register-serial prefix (neg, exclusive) and suffix (pos, inclusive) over 4 rows
    float vn[4], vp[4];
    #pragma unroll
    for (int r = 0; r < 4; r++) { vn[r] = en[r]*wh[r]; vp[r] = ep[r]*wh[r]; }
    float sn[4], sp[4];
    sn[0] = 0.f;   sn[1] = vn[0]; sn[2] = sn[1]+vn[1]; sn[3] = sn[2]+vn[2];
    const float totn = sn[3] + vn[3];
    sp[3] = vp[3]; sp[2] = sp[3]+vp[2]; sp[1] = sp[2]+vp[1]; sp[0] = sp[1]+vp[0];
    const float totp = sp[0];
    // scalar analogues
    float ssn[4], ssp[4];
    ssn[0] = 0.f;   ssn[1] = en[0]; ssn[2] = ssn[1]+en[1]; ssn[3] = ssn[2]+en[2];
    const float stotn = ssn[3] + en[3];
    ssp[3] = ep[3]; ssp[2] = ssp[3]+ep[2]; ssp[1] = ssp[2]+ep[1]; ssp[0] = ssp[1]+ep[0];
    const float stotp = ssp[0];

    totn_s[w][lane] = totn;
    totp_s[w][lane] = totp;
    if (lane == 0) { totn_s[w][32] = stotn; totp_s[w][32] = stotp; }
    __syncthreads();

    // cross-warp scans: warp w scans channel w (stride-35 = conflict-free)
    {
        float v1 = totn_s[lane][w];
        float i1 = warp_incl_scan(v1, lane);
        float e1 = __shfl_up_sync(0xffffffffu, i1, 1); if (lane == 0) e1 = 0.f;
        totn_s[lane][w] = e1;
        if (lane == 31) g_CnegT[(bh*NCH + c)*ND + w] = i1;

        float v2 = totp_s[31 - lane][w];
        float i2 = warp_incl_scan(v2, lane);
        float e2 = __shfl_up_sync(0xffffffffu, i2, 1); if (lane == 0) e2 = 0.f;
        totp_s[31 - lane][w] = e2;
        if (lane == 31) g_CposT[(bh*NCH + c)*ND + w] = i2;

        if (w == 0) {           // scalar neg column
            float v3 = totn_s[lane][32];
            float i3 = warp_incl_scan(v3, lane);
            float e3 = __shfl_up_sync(0xffffffffu, i3, 1); if (lane == 0) e3 = 0.f;
            totn_s[lane][32] = e3;
            if (lane == 31) g_pnT[bh*NCH + c] = i3;
        } else if (w == 1) {    // scalar pos column (suffix)
            float v3 = totp_s[31 - lane][32];
            float i3 = warp_incl_scan(v3, lane);
            float e3 = __shfl_up_sync(0xffffffffu, i3, 1); if (lane == 0) e3 = 0.f;
            totp_s[31 - lane][32] = e3;
            if (lane == 31) g_ppT[bh*NCH + c] = i3;
        }
    }
    __syncthreads();

    const float offn  = totn_s[w][lane];
    const float offp  = totp_s[w][lane];
    const float offsn = totn_s[w][32];
    const float offsp = totp_s[w][32];
    #pragma unroll
    for (int r = 0; r < 4; r++)
        g_S[((size_t)(row0 + r))*ND + lane] = make_float2(sn[r] + offn, sp[r] + offp);
    if (lane == 0) {
        #pragma unroll
        for (int r = 0; r < 4; r++)
            g_pL[row0 + r] = make_float2(ssn[r] + offsn, ssp[r] + offsp);
    }

    // completion counter; last-arriving block of this bh computes chunk offsets (vec + scalar)
    if (tid == 0) {
        __threadfence();
        isLast = (atomicAdd(&g_cnt[bh], 1) == NCH - 1);
    }
    __syncthreads();
    if (isLast) {
        if (w == 0) {
            __threadfence();
            float t[NCH];
            #pragma unroll
            for (int q = 0; q < NCH; q++) t[q] = g_CnegT[(bh*NCH + q)*ND + lane];
            float s = 0.f;
            #pragma unroll
            for (int q = 0; q < NCH; q++) {
                ((float*)g_Off)[(((size_t)bh*NCH + q)*ND + lane)*2 + 0] = s;
                s += t[q];
            }
            g_Tot2[bh*ND + lane] = make_float2(s, 0.f);
        } else if (w == 1) {
            __threadfence();
            float t[NCH];
            #pragma unroll
            for (int q = 0; q < NCH; q++) t[q] = g_CposT[(bh*NCH + q)*ND + lane];
            float s = 0.f;
            #pragma unroll
            for (int q = NCH-1; q >= 0; q--) {
                ((float*)g_Off)[(((size_t)bh*NCH + q)*ND + lane)*2 + 1] = s;
                s += t[q];
            }
        } else if (w == 2) {    // scalar neg chunk offsets
            __threadfence();
            float v = (lane < NCH) ? g_pnT[bh*NCH + lane] : 0.f;
            float inc = warp_incl_scan(v, lane);
            float exc = __shfl_up_sync(0xffffffffu, inc, 1); if (lane == 0) exc = 0.f;
            if (lane < NCH) g_opn[bh*(NCH+1) + lane] = exc;
            if (lane == NCH-1) g_opn[bh*(NCH+1) + NCH] = inc;
        } else if (w == 3) {    // scalar pos chunk offsets (suffix)
            __threadfence();
            float v = (lane < NCH) ? g_ppT[bh*NCH + (NCH-1-lane)] : 0.f;
            float inc = warp_incl_scan(v, lane);
            float exc = __shfl_up_sync(0xffffffffu, inc, 1); if (lane == 0) exc = 0.f;
            if (lane < NCH) g_opp[bh*NCH + (NCH-1-lane)] = exc;
        }
    }
}

// ---------------- kernel 5: pure streaming combine (PDL pre-wait prefetch) ----------------
__global__ void __launch_bounds__(256) k5f(float* __restrict__ out) {
    const int bh = blockIdx.y;
    const int b = bh >> 2, h = bh & 3;
    const int tid = threadIdx.x, warp = tid >> 5, lane = tid & 31;
    const int i0 = blockIdx.x*32 + warp*4;

    // pre-wait: g_lo/g_f12 are k2b outputs, complete by transitivity (k3 waited).
    // These loads overlap k3's execution.
    int lo_l = 0; float f1_l = 0.f, f2_l = 0.f;
    if (lane < 4) {
        lo_l = g_lo[bh*NN + i0 + lane];
        float2 f = g_f12[bh*NN + i0 + lane];
        f1_l = f.x; f2_l = f.y;
    }

    pdl_wait();      // k3 complete

    float pn_l = 0.f, pp_l = 0.f;
    if (lane < 4) {
        if (lo_l < NN) {
            const int c = lo_l >> 7;
            float2 pl = g_pL[bh*NN + lo_l];
            pn_l = pl.x + g_opn[bh*(NCH+1) + c];
            pp_l = pl.y + g_opp[bh*NCH + c];
        } else {
            pn_l = g_opn[bh*(NCH+1) + NCH];
            pp_l = 0.f;
        }
    }

    #pragma unroll
    for (int r = 0; r < 4; r++) {
        const int lo = __shfl_sync(0xffffffffu, lo_l, r);
        const float f1 = __shfl_sync(0xffffffffu, f1_l, r);
        const float f2 = __shfl_sync(0xffffffffu, f2_l, r);
        const float pn = __shfl_sync(0xffffffffu, pn_l, r);
        const float pp = __shfl_sync(0xffffffffu, pp_l, r);
        const int i = i0 + r;
        float sneg, spos;
        if (lo < NN) {
            const int c = lo >> 7;
            float2 S   = g_S  [((size_t)(bh*NN) + lo)*ND + lane];
            float2 off = g_Off[((size_t)bh*NCH + c)*ND + lane];
            sneg = S.x + off.x;
            spos = S.y + off.y;
        } else {
            float2 t = g_Tot2[bh*ND + lane];
            sneg = t.x;
            spos = t.y;
        }
        float num = f2*sneg + f1*spos;
        float den = f2*pn + f1*pp;
        float hv = __fdividef(num, den);
        float res = hv > 0.f ? hv : (__expf(hv) - 1.0f);
        out[((size_t)(b*NN + i))*(NH*ND) + h*ND + lane] = res;
    }
}

// ---------------- host ----------------
template <typename... Args, typename F>
static inline void launch_pdl(F func, dim3 grid, dim3 block, Args... args) {
    cudaLaunchConfig_t cfg = {};
    cfg.gridDim = grid;
    cfg.blockDim = block;
    cfg.dynamicSmemBytes = 0;
    cfg.stream = 0;
    cudaLaunchAttribute attr[1];
    attr[0].id = cudaLaunchAttributeProgrammaticStreamSerialization;
    attr[0].val.programmaticStreamSerializationAllowed = 1;
    cfg.attrs = attr;
    cfg.numAttrs = 1;
    cudaLaunchKernelEx(&cfg, func, args...);
}

extern "C" void kernel_launch(void* const* d_in, const int* in_sizes, int n_in,
                              void* d_out, int out_size) {
    (void)in_sizes; (void)n_in; (void)out_size;
    const float* x = (const float*)d_in[0];
    const float* W = (const float*)d_in[1];
    const float* a = (const float*)d_in[2];
    float* out = (float*)d_out;

    static int attr_set = 0;
    if (!attr_set) {
        cudaFuncSetAttribute(k1, cudaFuncAttributeMaxDynamicSharedMemorySize, SM1_BYTES);
        attr_set = 1;
    }

    k1<<<dim3(NN/128, NH, NB), 256, SM1_BYTES>>>(x, W, a);
    launch_pdl(k2a, dim3(NSEG, BHD), dim3(256));
    launch_pdl(k2b, dim3(NSEG, BHD), dim3(512));
    launch_pdl(k3,  dim3(NCH, BHD),  dim3(1024));
    launch_pdl(k5f, dim3(NN/32, BHD), dim3(256), out);
}